// round 4
// baseline (speedup 1.0000x reference)
#include <cuda_runtime.h>

#define NN 256
#define BB 64
#define GAMMA 0.01f
#define INVG 100.0f
#define FBIG 1e8f
#define CHUNK 16
#define NCHUNK 18                    // 18*16 = 288 iterations per warp per direction
#define LAG 3                        // chunks of pipeline skew between adjacent warps
#define STEPS (NCHUNK + LAG * 7)     // 39 lockstep steps per direction
#define FULL 0xffffffffu

// R scratch, diagonal-major per batch (coalesced for the ladder). 16 MB -> L2.
__device__ float g_R[BB * NN * NN];
__device__ float g_partV[BB];
__device__ float g_partE[BB];
__device__ unsigned g_ticket = 0;

__device__ __forceinline__ int diag_start(int d) {
    // start offset of anti-diagonal d (d in [2, 2N]) in diagonal-major storage
    return (d <= NN + 1)
        ? (((d - 1) * (d - 2)) >> 1)
        : (NN * NN - (((2 * NN + 1 - d) * (2 * NN + 2 - d)) >> 1));
}

__global__ __launch_bounds__(256) void dilate_fb_kernel(
    const float* __restrict__ y_pred,
    const float* __restrict__ y_true,
    float* __restrict__ out)
{
    __shared__ float s_o[NN], s_t[NN];
    __shared__ float vrow[7][NN + 2];   // forward boundary rows V[32(w+1)][j]
    __shared__ float erow[7][NN + 2];   // backward boundary rows E[32w+33][j]
    __shared__ float rrow[7][NN + 2];   // backward boundary rows R[32w+33][j]
    __shared__ float s_red[8];
    __shared__ float s_vnn;
    __shared__ int   s_last;

    const int b    = blockIdx.x;
    const int tid  = threadIdx.x;
    const int w    = tid >> 5;
    const int l    = tid & 31;
    const int base = w << 5;
    const int i    = base + l + 1;      // owned DP row (1..256)

    s_o[tid] = y_pred[b * NN + tid];
    s_t[tid] = y_true[b * NN + tid];
    __syncthreads();

    const float ti  = s_t[i - 1];
    const float tip = (i < NN) ? s_t[i] : 0.0f;
    float* __restrict__ Rb = g_R + (size_t)b * (NN * NN);

    // ================= FORWARD (warp ladder, lockstep) =================
    // lane l at iter t computes (i, j = t-l+1); all lanes share diag d = base+t+2.
    // Warp w runs chunk c at step s = c + LAG*w; producer w-1 finished chunk c+2
    // at step c+2+LAG*(w-1) = s-1, separated by __syncthreads.
    {
        float vleft = FBIG, vup = FBIG, vdiag = FBIG;
        const float* vcons = vrow[(w > 0) ? (w - 1) : 0];   // w==0 never reads
        int d = base + 2;
        int dstart = diag_start(base + 2);
        const int myoff = LAG * w;

        for (int s = 0; s < STEPS; ++s) {
            const int c = s - myoff;
            if (c >= 0 && c < NCHUNK) {
                #pragma unroll
                for (int k = 0; k < CHUNK; ++k) {
                    const int t = c * CHUNK + k;
                    const bool act = (t >= l) && (t <= l + (NN - 1));
                    if (t == l) {               // first active iter: column-0 boundary
                        vleft = FBIG;
                        if (l == 0) {
                            vdiag = (w == 0) ? 0.0f : FBIG;   // V[0][0]=0 else BIG
                            vup   = (w == 0) ? FBIG : vcons[1];
                        } else {
                            vdiag = FBIG;
                        }
                    }
                    float vv = FBIG;
                    if (act) {
                        float m = fminf(vleft, fminf(vup, vdiag));
                        float ssum = __expf((m - vleft) * INVG)
                                   + __expf((m - vup)   * INVG)
                                   + __expf((m - vdiag) * INVG);
                        float diff = ti - s_o[t - l];
                        vv = fmaf(diff, diff, m) - GAMMA * __logf(ssum);
                        int imin = max(1, d - NN);
                        Rb[dstart + (i - imin)] = vv;               // coalesced
                        if (l == 31 && w < 7) vrow[w][t - 30] = vv; // boundary row
                        if (d == 2 * NN) s_vnn = vv;                // V[N][N]
                    }
                    float vsh = __shfl_up_sync(FULL, vv, 1);        // V[i-1][j+1]
                    if (l == 0)
                        vsh = (w == 0) ? FBIG : vcons[(t + 2 <= NN) ? (t + 2) : NN];
                    vdiag = vup;
                    vup   = vsh;
                    vleft = vv;
                    dstart += (d <= NN + 1) ? (d - 1) : (2 * NN + 1 - d);
                    d += 1;
                }
            }
            __syncthreads();
        }
    }

    // ================= BACKWARD (warp ladder, lockstep, reversed) =================
    // lane l at iter t computes (i, j = 287-t-l); diag d = base+288-t.
    float sumE = 0.0f;
    {
        float eprev = 0.0f, rprev = 0.0f;
        float edown = 0.0f, rdown = 0.0f;
        float ediag = 0.0f, rdiag = 0.0f;
        const float* econs = erow[(w < 7) ? w : 0];   // w==7 never reads
        const float* rcons = rrow[(w < 7) ? w : 0];
        float rb_cur[CHUNK], rb_nxt[CHUNK];

        // prefetch chunk 0 (own-lane R values; written by own forward)
        #pragma unroll
        for (int k = 0; k < CHUNK; ++k) {
            int t  = k;
            int j  = (NN + 31) - t - l;
            int dd = base + (NN + 32) - t;
            bool ok = (j >= 1) && (j <= NN);
            int imin = max(1, dd - NN);
            rb_cur[k] = ok ? __ldg(Rb + diag_start(dd) + (i - imin)) : 0.0f;
        }

        const int myoff = LAG * (7 - w);
        for (int s = 0; s < STEPS; ++s) {
            const int c = s - myoff;
            if (c >= 0 && c < NCHUNK) {
                if (c + 1 < NCHUNK) {           // prefetch next chunk (overlaps compute)
                    #pragma unroll
                    for (int k = 0; k < CHUNK; ++k) {
                        int t  = (c + 1) * CHUNK + k;
                        int j  = (NN + 31) - t - l;
                        int dd = base + (NN + 32) - t;
                        bool ok = (j >= 1) && (j <= NN);
                        int imin = max(1, dd - NN);
                        rb_nxt[k] = ok ? __ldg(Rb + diag_start(dd) + (i - imin)) : 0.0f;
                    }
                }
                #pragma unroll
                for (int k = 0; k < CHUNK; ++k) {
                    const int t = c * CHUNK + k;
                    const int j = (NN + 31) - t - l;
                    const bool act = (j >= 1) && (j <= NN);
                    if (t == 31 - l) {          // first active iter (col 256)
                        eprev = 0.0f; rprev = 0.0f; ediag = 0.0f; rdiag = 0.0f;
                        if (l == 31) {
                            edown = (w < 7) ? econs[NN] : 0.0f;
                            rdown = (w < 7) ? rcons[NN] : 0.0f;
                        }
                    }
                    float Rcur = rb_cur[k];
                    float ee = 0.0f;
                    if (act) {
                        if (i == NN && j == NN) {
                            ee = 1.0f;
                        } else {
                            if (i < NN) {           // down neighbor (i+1, j)
                                float dd = tip - s_o[j - 1];
                                ee = __expf((rdown - Rcur - dd * dd) * INVG) * edown;
                            }
                            if (j < NN) {           // right neighbor (i, j+1)
                                float dd = ti - s_o[j];
                                ee = fmaf(__expf((rprev - Rcur - dd * dd) * INVG), eprev, ee);
                            }
                            if (i < NN && j < NN) { // diag neighbor (i+1, j+1)
                                float dd = tip - s_o[j];
                                ee = fmaf(__expf((rdiag - Rcur - dd * dd) * INVG), ediag, ee);
                            }
                        }
                        float wij = (float)(i - j);
                        sumE = fmaf(ee, wij * wij, sumE);
                        if (l == 0 && w > 0) { erow[w - 1][j] = ee; rrow[w - 1][j] = Rcur; }
                    }
                    float esh = __shfl_down_sync(FULL, ee, 1);      // E[i+1][j-1]
                    float rsh = __shfl_down_sync(FULL, Rcur, 1);
                    if (l == 31) {
                        int col = NN - (t + 1);
                        bool ok2 = (w < 7) && (col >= 1);
                        esh = ok2 ? econs[col] : 0.0f;
                        rsh = ok2 ? rcons[col] : 0.0f;
                    }
                    ediag = edown; rdiag = rdown;
                    edown = esh;   rdown = rsh;
                    eprev = ee;    rprev = Rcur;
                }
                #pragma unroll
                for (int k = 0; k < CHUNK; ++k) rb_cur[k] = rb_nxt[k];
            }
            __syncthreads();
        }
    }

    // ---- reduce sum(E * omega): warp shfl tree, then 8 partials ----
    #pragma unroll
    for (int off = 16; off > 0; off >>= 1)
        sumE += __shfl_down_sync(FULL, sumE, off);
    if (l == 0) s_red[w] = sumE;
    __syncthreads();

    // ---- per-block partials + deterministic last-block finalize ----
    if (tid == 0) {
        float se = 0.0f;
        #pragma unroll
        for (int q = 0; q < 8; ++q) se += s_red[q];
        g_partV[b] = s_vnn;
        g_partE[b] = se;
        __threadfence();
        unsigned tk = atomicAdd(&g_ticket, 1u);
        s_last = (tk == BB - 1) ? 1 : 0;
    }
    __syncthreads();
    if (s_last && tid < 32) {
        __threadfence();
        float sv = __ldcg(&g_partV[tid]) + __ldcg(&g_partV[tid + 32]);
        float se = __ldcg(&g_partE[tid]) + __ldcg(&g_partE[tid + 32]);
        #pragma unroll
        for (int off = 16; off > 0; off >>= 1) {
            sv += __shfl_down_sync(FULL, sv, off);
            se += __shfl_down_sync(FULL, se, off);
        }
        if (tid == 0) {
            float loss_shape    = sv * (1.0f / (float)BB);
            float loss_temporal = se * (1.0f / ((float)BB * (float)(NN * NN)));
            out[0] = 0.5f * loss_shape + 0.5f * loss_temporal;
            g_ticket = 0;   // reset for next launch (graph replay safe)
        }
    }
}

extern "C" void kernel_launch(void* const* d_in, const int* in_sizes, int n_in,
                              void* d_out, int out_size) {
    const float* y_pred = (const float*)d_in[0];
    const float* y_true = (const float*)d_in[1];
    dilate_fb_kernel<<<BB, 256>>>(y_pred, y_true, (float*)d_out);
}

// round 5
// speedup vs baseline: 1.4940x; 1.4940x over previous
#include <cuda_runtime.h>

#define NN 256
#define BB 64
#define FBIG 1e8f
#define NBIG (-1e8f)
#define K2   144.269504089f     // (1/gamma) * log2(e), gamma = 0.01
#define GLN2 0.006931471806f    // gamma * ln(2)
#define CHUNK 8
#define NCHUNK 36               // ceil(287/8) -> 288 iters per warp per pass
#define LAG 5                   // producer chunk c+4 done at step s-1 (proof in notes)
#define STEPS (NCHUNK + LAG*3)  // 51 lockstep steps per pass (4 warps)
#define FULL 0xffffffffu

// R scratch, diagonal-major per batch (coalesced along the wavefront). 16MB -> L2.
__device__ float g_R[BB * NN * NN];
__device__ float g_partV[BB];
__device__ float g_partE[BB];
__device__ unsigned g_ticket = 0;

__device__ __forceinline__ float ex2(float x) { float r; asm("ex2.approx.f32 %0, %1;" : "=f"(r) : "f"(x)); return r; }
__device__ __forceinline__ float lg2(float x) { float r; asm("lg2.approx.f32 %0, %1;" : "=f"(r) : "f"(x)); return r; }

__device__ __forceinline__ int diag_start(int d) {
    // start of anti-diagonal d (d in [2, 2N]) in diagonal-major storage
    return (d <= NN + 1) ? (((d - 1) * (d - 2)) >> 1)
                         : (NN * NN - (((2 * NN + 1 - d) * (2 * NN + 2 - d)) >> 1));
}
__device__ __forceinline__ int roff(int d, int i) {
    return diag_start(d) + i - max(1, d - NN);
}

__global__ __launch_bounds__(128, 1) void dilate_fb_kernel(
    const float* __restrict__ y_pred,
    const float* __restrict__ y_true,
    float* __restrict__ out)
{
    __shared__ float s_o[NN], s_t[NN];
    __shared__ float vrow[3][NN + 2];   // forward boundary rows V[64(w+1)][q]
    __shared__ float erow[3][NN + 2];   // backward boundary rows E'[64(w+1)][q]
    __shared__ float rrow[3][NN + 2];   // backward boundary rows R'[64(w+1)][q]
    __shared__ float s_red[4];
    __shared__ int   s_last;

    const int b   = blockIdx.x;
    const int tid = threadIdx.x;
    const int w   = tid >> 5;
    const int l   = tid & 31;
    const int i0  = (w << 6) + 2 * l + 1;   // forward rows i0, i0+1 (1..256)
    const int i1  = i0 + 1;

    s_o[tid]       = y_pred[b * NN + tid];
    s_o[tid + 128] = y_pred[b * NN + tid + 128];
    s_t[tid]       = y_true[b * NN + tid];
    s_t[tid + 128] = y_true[b * NN + tid + 128];
    for (int x = tid; x < 3 * (NN + 2); x += 128) {
        (&vrow[0][0])[x] = FBIG;
        (&erow[0][0])[x] = 0.0f;
        (&rrow[0][0])[x] = NBIG;
    }
    __syncthreads();

    const float ti0 = s_t[i0 - 1];
    const float ti1 = s_t[i1 - 1];
    float* __restrict__ Rb = g_R + (size_t)b * (NN * NN);
    const float* vcons = vrow[(w > 0) ? (w - 1) : 0];   // w==0 never uses content
    const float* econs = erow[(w > 0) ? (w - 1) : 0];
    const float* rcons = rrow[(w > 0) ? (w - 1) : 0];

    // ================= FORWARD (2 rows/lane warp ladder, lockstep) =================
    // lane l at iter t computes column q = t-l+1 for rows i0,i1. Active: 0<=t-l<256.
    float vnn = 0.0f;
    {
        float v0 = FBIG, v1 = FBIG;           // own left values V[i][q-1]
        float shA = FBIG, shB = FBIG;         // lane l-1 row-2 values (t-1, t-2)
        float lz_up = FBIG, lz_dg = FBIG;     // lane-0 vcons pipeline

        for (int s = 0; s < STEPS; ++s) {
            const int c = s - LAG * w;
            if (c >= 0 && c < NCHUNK) {
                if (c == 0 && l == 0) {
                    lz_up = (w > 0) ? vcons[1] : FBIG;
                    lz_dg = (w == 0) ? 0.0f : FBIG;    // V[0][0]=0 only for (1,1)
                }
                #pragma unroll
                for (int k = 0; k < CHUNK; ++k) {
                    const int t = c * CHUNK + k;
                    const int q = t - l + 1;
                    const bool act = (unsigned)(t - l) < NN;
                    float up0 = (l == 0) ? lz_up : shA;   // V[i0-1][q]
                    float dg0 = (l == 0) ? lz_dg : shB;   // V[i0-1][q-1]
                    float oj  = s_o[act ? (q - 1) : 0];
                    // row-1 cell
                    float m0  = fminf(v0, fminf(up0, dg0));
                    float ss0 = ex2((m0 - v0) * K2) + ex2((m0 - up0) * K2)
                              + ex2((m0 - dg0) * K2);
                    float df0 = ti0 - oj;
                    float nv0 = fmaf(df0, df0, m0) - GLN2 * lg2(ss0);
                    // row-2 cell: up = nv0 (this iter), diag = v0 (old row-1 left)
                    float m1  = fminf(v1, fminf(nv0, v0));
                    float ss1 = ex2((m1 - v1) * K2) + ex2((m1 - nv0) * K2)
                              + ex2((m1 - v0) * K2);
                    float df1 = ti1 - oj;
                    float nv1 = fmaf(df1, df1, m1) - GLN2 * lg2(ss1);
                    if (!act) { nv0 = FBIG; nv1 = FBIG; }
                    if (act) {
                        int d0 = i0 + q;
                        Rb[roff(d0, i0)]     = nv0;
                        Rb[roff(d0 + 1, i1)] = nv1;
                        if (l == 31) {
                            if (w < 3) vrow[w][q] = nv1;
                            else if (q == NN) vnn = nv1;   // V[N][N]
                        }
                    }
                    float shN = __shfl_up_sync(FULL, nv1, 1);
                    shB = shA; shA = shN;
                    if (l == 0) {
                        lz_dg = lz_up;
                        int qn = t + 2; if (qn > NN + 1) qn = NN + 1;
                        lz_up = (w > 0) ? vcons[qn] : FBIG;
                    }
                    v0 = nv0; v1 = nv1;
                }
            }
            __syncthreads();
        }
    }
    if (w == 3 && l == 31) g_partV[b] = vnn;

    // ================= BACKWARD as mirrored forward =================
    // Reversed coords: p = N+1-i, q = N+1-j. E'[p,q] dep on (p-1,q),(p,q-1),(p-1,q-1).
    // Warp w owns p-rows 64w+1..64w+64; lane l owns p0=64w+2l+1, p1=p0+1.
    // Orig rows iA=N+1-p0, iB=iA-1; orig col jg=N+1-q.
    float sumE = 0.0f;
    {
        const int p0 = i0;                    // same formula as forward rows
        const int iA = NN + 1 - p0;
        const int iB = iA - 1;
        int tAi = NN - p0 + 1; if (tAi > NN - 1) tAi = NN - 1;  // clamp (unused when p0==1)
        const float tA = s_t[tAi];            // t'_{p0-1}
        const float tB = s_t[NN - p0];        // t'_{p0}
        const float tC = s_t[NN - p0 - 1 >= 0 ? NN - p0 - 1 : 0];  // t'_{p1}

        float e0 = 0.0f, e1 = 0.0f;           // own E'[p][q-1]
        float r0 = NBIG, r1 = NBIG;           // own R'[p][q-1]
        float shEA = 0.0f, shEB = 0.0f;       // lane l-1 row-2 E' (t-1, t-2)
        float shRA = NBIG, shRB = NBIG;
        float lzE_up = 0.0f, lzE_dg = 0.0f;   // lane-0 cons pipeline
        float lzR_up = NBIG, lzR_dg = NBIG;
        float oqm1 = 0.0f;                    // o'_{q-1}
        float rcA[CHUNK], rcB[CHUNK], rnA[CHUNK], rnB[CHUNK];

        // prefetch chunk 0 own R' rows (forward pass complete: loop ended with barrier)
        #pragma unroll
        for (int k = 0; k < CHUNK; ++k) {
            int t = k, q = t - l + 1;
            bool act = (unsigned)(t - l) < NN;
            int jg = NN + 1 - q, dA = iA + jg;
            rcA[k] = act ? __ldg(Rb + roff(dA,     iA)) : NBIG;
            rcB[k] = act ? __ldg(Rb + roff(dA - 1, iB)) : NBIG;
        }

        for (int s = 0; s < STEPS; ++s) {
            const int c = s - LAG * w;
            if (c >= 0 && c < NCHUNK) {
                if (c + 1 < NCHUNK) {         // prefetch next chunk
                    #pragma unroll
                    for (int k = 0; k < CHUNK; ++k) {
                        int t = (c + 1) * CHUNK + k, q = t - l + 1;
                        bool act = (unsigned)(t - l) < NN;
                        int jg = NN + 1 - q, dA = iA + jg;
                        rnA[k] = act ? __ldg(Rb + roff(dA,     iA)) : NBIG;
                        rnB[k] = act ? __ldg(Rb + roff(dA - 1, iB)) : NBIG;
                    }
                }
                if (c == 0 && l == 0) {
                    lzE_up = (w > 0) ? econs[1] : 0.0f;
                    lzR_up = (w > 0) ? rcons[1] : NBIG;
                    lzE_dg = 0.0f; lzR_dg = NBIG;
                }
                #pragma unroll
                for (int k = 0; k < CHUNK; ++k) {
                    const int t = c * CHUNK + k;
                    const int q = t - l + 1;
                    const bool act = (unsigned)(t - l) < NN;
                    float Eup = (l == 0) ? lzE_up : shEA;  // E'[p0-1][q]
                    float Rup = (l == 0) ? lzR_up : shRA;
                    float Edg = (l == 0) ? lzE_dg : shEB;  // E'[p0-1][q-1]
                    float Rdg = (l == 0) ? lzR_dg : shRB;
                    float oq  = s_o[act ? (NN - q) : 0];   // o'_q
                    float RA  = rcA[k];
                    float RB  = rcB[k];
                    // row-1 (p0)
                    float dA0 = tA - oq,   dB0 = tB - oqm1, dC0 = tA - oqm1;
                    float ne0 = ex2(fmaf(-dA0, dA0, Rup - RA) * K2) * Eup
                              + ex2(fmaf(-dB0, dB0, r0  - RA) * K2) * e0
                              + ex2(fmaf(-dC0, dC0, Rdg - RA) * K2) * Edg;
                    if (w == 0 && l == 0 && t == 0) ne0 = 1.0f;   // E[N][N]
                    // row-2 (p1): down = row-1 this iter, diag = row-1 prev iter
                    float dA1 = tB - oq,   dB1 = tC - oqm1, dC1 = tB - oqm1;
                    float ne1 = ex2(fmaf(-dA1, dA1, RA - RB) * K2) * ne0
                              + ex2(fmaf(-dB1, dB1, r1 - RB) * K2) * e1
                              + ex2(fmaf(-dC1, dC1, r0 - RB) * K2) * e0;
                    if (!act) { ne0 = 0.0f; ne1 = 0.0f; RA = NBIG; RB = NBIG; }
                    // omega = (i-j)^2 = (q-p)^2
                    float wq0 = (float)(q - p0);
                    sumE = fmaf(ne0, wq0 * wq0, sumE);
                    float wq1 = wq0 - 1.0f;
                    sumE = fmaf(ne1, wq1 * wq1, sumE);
                    if (act && l == 31 && w < 3) { erow[w][q] = ne1; rrow[w][q] = RB; }
                    float shEN = __shfl_up_sync(FULL, ne1, 1);
                    float shRN = __shfl_up_sync(FULL, RB, 1);
                    shEB = shEA; shEA = shEN;
                    shRB = shRA; shRA = shRN;
                    if (l == 0) {
                        lzE_dg = lzE_up; lzR_dg = lzR_up;
                        int qn = t + 2; if (qn > NN + 1) qn = NN + 1;
                        lzE_up = (w > 0) ? econs[qn] : 0.0f;
                        lzR_up = (w > 0) ? rcons[qn] : NBIG;
                    }
                    e0 = ne0; r0 = RA; e1 = ne1; r1 = RB; oqm1 = oq;
                }
                #pragma unroll
                for (int k = 0; k < CHUNK; ++k) { rcA[k] = rnA[k]; rcB[k] = rnB[k]; }
            }
            __syncthreads();
        }
    }

    // ---- reduce sum(E * omega): warp shfl tree, then 4 partials ----
    #pragma unroll
    for (int off = 16; off > 0; off >>= 1)
        sumE += __shfl_down_sync(FULL, sumE, off);
    if (l == 0) s_red[w] = sumE;
    __syncthreads();

    // ---- per-block partials + deterministic last-block finalize ----
    if (tid == 0) {
        g_partE[b] = s_red[0] + s_red[1] + s_red[2] + s_red[3];
        __threadfence();
        unsigned tk = atomicAdd(&g_ticket, 1u);
        s_last = (tk == BB - 1) ? 1 : 0;
    }
    __syncthreads();
    if (s_last && tid < 32) {
        __threadfence();
        float sv = __ldcg(&g_partV[tid]) + __ldcg(&g_partV[tid + 32]);
        float se = __ldcg(&g_partE[tid]) + __ldcg(&g_partE[tid + 32]);
        #pragma unroll
        for (int off = 16; off > 0; off >>= 1) {
            sv += __shfl_down_sync(FULL, sv, off);
            se += __shfl_down_sync(FULL, se, off);
        }
        if (tid == 0) {
            float loss_shape    = sv * (1.0f / (float)BB);
            float loss_temporal = se * (1.0f / ((float)BB * (float)(NN * NN)));
            out[0] = 0.5f * loss_shape + 0.5f * loss_temporal;
            g_ticket = 0;   // reset for graph replay
        }
    }
}

extern "C" void kernel_launch(void* const* d_in, const int* in_sizes, int n_in,
                              void* d_out, int out_size) {
    const float* y_pred = (const float*)d_in[0];
    const float* y_true = (const float*)d_in[1];
    dilate_fb_kernel<<<BB, 128>>>(y_pred, y_true, (float*)d_out);
}